// round 9
// baseline (speedup 1.0000x reference)
#include <cuda_runtime.h>
#include <cstdint>
#include <cstddef>

// ---------------- problem constants ----------------
#define HID   3072
#define HEADS 24
#define HD    128
#define SEQL  2048
#define MLP   12288
#define H1    (3*HID + MLP)   // 21504 = lin1 out
#define C2K   (HID + MLP)     // 15360 = lin2 in

// ---------------- device scratch (static, no allocations) ----------------
__device__ float g_svec[HID];                          // silu(vec)
__device__ float g_mod [3*HID];                        // shift | scale | gate
__device__ float g_xmod[(size_t)SEQL*HID];             // modulated LN(x)
__device__ float g_h   [(size_t)SEQL*H1];              // lin1 output
__device__ float g_q   [(size_t)HEADS*SEQL*HD];        // q (rope'd, pre-scaled)
__device__ float g_k   [(size_t)HEADS*SEQL*HD];        // k (rope'd)
__device__ float g_vt  [(size_t)HEADS*HD*SEQL];        // v transposed [h][d][l]
__device__ float g_s   [(size_t)HEADS*SEQL*SEQL];      // scores / probs
__device__ float g_c   [(size_t)SEQL*C2K];             // concat(attn, gelu(mlp))

// ---------------- helpers ----------------
__device__ __forceinline__ float to_tf32(float x) {
    uint32_t u;
    asm("cvt.rna.tf32.f32 %0, %1;" : "=r"(u) : "f"(x));
    return __uint_as_float(u);
}

__device__ __forceinline__ void mma8(float* d, const uint32_t* a, const uint32_t* b) {
    asm volatile(
        "mma.sync.aligned.m16n8k8.row.col.f32.tf32.tf32.f32 "
        "{%0,%1,%2,%3}, {%4,%5,%6,%7}, {%8,%9}, {%0,%1,%2,%3};\n"
        : "+f"(d[0]), "+f"(d[1]), "+f"(d[2]), "+f"(d[3])
        : "r"(a[0]), "r"(a[1]), "r"(a[2]), "r"(a[3]), "r"(b[0]), "r"(b[1]));
}

__device__ __forceinline__ float gelu1(float x) {
    float x3 = x * x * x;
    return 0.5f * x * (1.f + tanhf(0.7978845608028654f * (x + 0.044715f * x3)));
}

// ================= GEMM: C[b,m,n] = sum_k A[b,m,k]*B[b,n,k] (+bias)(*gate)(+resid) ===========
// TF32 tensor-core NT GEMM. All dims must be exact multiples of tiles (they are).
#define BM 128
#define BN 128
#define BKT 16
#define SPAD 8

__global__ __launch_bounds__(256)
void gemm_nt(const float* __restrict__ A, const float* __restrict__ B,
             const float* __restrict__ bias, const float* __restrict__ resid,
             const float* __restrict__ gate, float* __restrict__ C,
             int K, int lda, int ldb, int ldc,
             long long sA, long long sB, long long sC)
{
    __shared__ float As[2][BKT][BM + SPAD];
    __shared__ float Bs[2][BKT][BN + SPAD];

    const int tid  = threadIdx.x;
    const int lane = tid & 31;
    const int gid  = lane >> 2;
    const int tg   = lane & 3;
    const int warp = tid >> 5;
    const int wm   = (warp >> 2) * 64;   // 0 or 64
    const int wn   = (warp & 3) * 32;    // 0..96

    const int bm0 = blockIdx.y * BM;
    const int bn0 = blockIdx.x * BN;

    const float* Ab = A + (size_t)blockIdx.z * sA + (size_t)bm0 * lda;
    const float* Bb = B + (size_t)blockIdx.z * sB + (size_t)bn0 * ldb;

    const int fr = tid >> 2;         // row 0..63 (also +64)
    const int fk = (tid & 3) * 4;    // k-subvector

    float acc[4][4][4];
    #pragma unroll
    for (int i = 0; i < 4; ++i)
        #pragma unroll
        for (int j = 0; j < 4; ++j)
            #pragma unroll
            for (int v = 0; v < 4; ++v) acc[i][j][v] = 0.f;

    // prologue: tile 0 -> stage 0
    {
        float4 a0 = *(const float4*)(Ab + (size_t)fr * lda + fk);
        float4 a1 = *(const float4*)(Ab + (size_t)(fr + 64) * lda + fk);
        float4 b0 = *(const float4*)(Bb + (size_t)fr * ldb + fk);
        float4 b1 = *(const float4*)(Bb + (size_t)(fr + 64) * ldb + fk);
        As[0][fk+0][fr]    = to_tf32(a0.x); As[0][fk+1][fr]    = to_tf32(a0.y);
        As[0][fk+2][fr]    = to_tf32(a0.z); As[0][fk+3][fr]    = to_tf32(a0.w);
        As[0][fk+0][fr+64] = to_tf32(a1.x); As[0][fk+1][fr+64] = to_tf32(a1.y);
        As[0][fk+2][fr+64] = to_tf32(a1.z); As[0][fk+3][fr+64] = to_tf32(a1.w);
        Bs[0][fk+0][fr]    = to_tf32(b0.x); Bs[0][fk+1][fr]    = to_tf32(b0.y);
        Bs[0][fk+2][fr]    = to_tf32(b0.z); Bs[0][fk+3][fr]    = to_tf32(b0.w);
        Bs[0][fk+0][fr+64] = to_tf32(b1.x); Bs[0][fk+1][fr+64] = to_tf32(b1.y);
        Bs[0][fk+2][fr+64] = to_tf32(b1.z); Bs[0][fk+3][fr+64] = to_tf32(b1.w);
    }
    __syncthreads();

    const int nk = K / BKT;
    int s = 0;
    for (int kt = 0; kt < nk; ++kt) {
        float4 na0, na1, nb0, nb1;
        const bool hn = (kt + 1) < nk;
        if (hn) {
            const int k0 = (kt + 1) * BKT;
            na0 = *(const float4*)(Ab + (size_t)fr * lda + k0 + fk);
            na1 = *(const float4*)(Ab + (size_t)(fr + 64) * lda + k0 + fk);
            nb0 = *(const float4*)(Bb + (size_t)fr * ldb + k0 + fk);
            nb1 = *(const float4*)(Bb + (size_t)(fr + 64) * ldb + k0 + fk);
        }
        #pragma unroll
        for (int kk = 0; kk < BKT; kk += 8) {
            uint32_t af[4][4], bf[4][2];
            #pragma unroll
            for (int im = 0; im < 4; ++im) {
                const int m = wm + im * 16 + gid;
                af[im][0] = __float_as_uint(As[s][kk + tg    ][m]);
                af[im][1] = __float_as_uint(As[s][kk + tg    ][m + 8]);
                af[im][2] = __float_as_uint(As[s][kk + tg + 4][m]);
                af[im][3] = __float_as_uint(As[s][kk + tg + 4][m + 8]);
            }
            #pragma unroll
            for (int in = 0; in < 4; ++in) {
                const int n = wn + in * 8 + gid;
                bf[in][0] = __float_as_uint(Bs[s][kk + tg    ][n]);
                bf[in][1] = __float_as_uint(Bs[s][kk + tg + 4][n]);
            }
            #pragma unroll
            for (int im = 0; im < 4; ++im)
                #pragma unroll
                for (int in = 0; in < 4; ++in)
                    mma8(acc[im][in], af[im], bf[in]);
        }
        if (hn) {
            const int t = s ^ 1;
            As[t][fk+0][fr]    = to_tf32(na0.x); As[t][fk+1][fr]    = to_tf32(na0.y);
            As[t][fk+2][fr]    = to_tf32(na0.z); As[t][fk+3][fr]    = to_tf32(na0.w);
            As[t][fk+0][fr+64] = to_tf32(na1.x); As[t][fk+1][fr+64] = to_tf32(na1.y);
            As[t][fk+2][fr+64] = to_tf32(na1.z); As[t][fk+3][fr+64] = to_tf32(na1.w);
            Bs[t][fk+0][fr]    = to_tf32(nb0.x); Bs[t][fk+1][fr]    = to_tf32(nb0.y);
            Bs[t][fk+2][fr]    = to_tf32(nb0.z); Bs[t][fk+3][fr]    = to_tf32(nb0.w);
            Bs[t][fk+0][fr+64] = to_tf32(nb1.x); Bs[t][fk+1][fr+64] = to_tf32(nb1.y);
            Bs[t][fk+2][fr+64] = to_tf32(nb1.z); Bs[t][fk+3][fr+64] = to_tf32(nb1.w);
            __syncthreads();
            s = t;
        }
    }

    // epilogue
    float* Cb = C + (size_t)blockIdx.z * sC;
    #pragma unroll
    for (int im = 0; im < 4; ++im) {
        #pragma unroll
        for (int in = 0; in < 4; ++in) {
            const int r  = bm0 + wm + im * 16 + gid;
            const int cc = bn0 + wn + in * 8 + 2 * tg;
            #pragma unroll
            for (int v = 0; v < 4; ++v) {
                const int rr = r + (v >> 1) * 8;
                const int c2 = cc + (v & 1);
                float val = acc[im][in][v];
                if (bias)  val += __ldg(bias + c2);
                if (gate)  val *= __ldg(gate + c2);
                if (resid) val += __ldg(resid + (size_t)rr * ldc + c2);
                Cb[(size_t)rr * ldc + c2] = val;
            }
        }
    }
}

// ================= small kernels =================

__global__ void silu_k(const float* __restrict__ v) {
    int i = blockIdx.x * blockDim.x + threadIdx.x;
    float x = v[i];
    g_svec[i] = x / (1.f + __expf(-x));
}

// m[i] = dot(silu(vec), mod_w[i,:]) + mod_b[i]   (one warp per output row)
__global__ __launch_bounds__(256)
void mod_gemv(const float* __restrict__ W, const float* __restrict__ b) {
    const int warp = threadIdx.x >> 5, lane = threadIdx.x & 31;
    const int row  = blockIdx.x * 8 + warp;
    const float* w = W + (size_t)row * HID;
    float s = 0.f;
    for (int j = lane * 4; j < HID; j += 128) {
        float4 wv = *(const float4*)(w + j);
        float4 vv = *(const float4*)(g_svec + j);
        s += wv.x * vv.x + wv.y * vv.y + wv.z * vv.z + wv.w * vv.w;
    }
    #pragma unroll
    for (int o = 16; o; o >>= 1) s += __shfl_down_sync(0xffffffffu, s, o);
    if (!lane) g_mod[row] = s + b[row];
}

// x_mod = (1+scale)*LN(x) + shift, one block per row
__global__ __launch_bounds__(256)
void ln_mod(const float* __restrict__ x) {
    const int l = blockIdx.x, tid = threadIdx.x;
    const float* xr = x + (size_t)l * HID;
    float4 v[3];
    float sum = 0.f, ss = 0.f;
    #pragma unroll
    for (int i = 0; i < 3; ++i) {
        v[i] = *(const float4*)(xr + (tid + i * 256) * 4);
        sum += v[i].x + v[i].y + v[i].z + v[i].w;
        ss  += v[i].x * v[i].x + v[i].y * v[i].y + v[i].z * v[i].z + v[i].w * v[i].w;
    }
    __shared__ float rs[2][8];
    #pragma unroll
    for (int o = 16; o; o >>= 1) {
        sum += __shfl_down_sync(0xffffffffu, sum, o);
        ss  += __shfl_down_sync(0xffffffffu, ss,  o);
    }
    if (!(tid & 31)) { rs[0][tid >> 5] = sum; rs[1][tid >> 5] = ss; }
    __syncthreads();
    sum = 0.f; ss = 0.f;
    #pragma unroll
    for (int i = 0; i < 8; ++i) { sum += rs[0][i]; ss += rs[1][i]; }
    const float mu   = sum * (1.f / HID);
    const float var  = ss * (1.f / HID) - mu * mu;
    const float rstd = rsqrtf(var + 1e-6f);
    #pragma unroll
    for (int i = 0; i < 3; ++i) {
        const int c = (tid + i * 256) * 4;
        float4 sh = *(const float4*)(g_mod + c);
        float4 sc = *(const float4*)(g_mod + HID + c);
        float4 o;
        o.x = (1.f + sc.x) * ((v[i].x - mu) * rstd) + sh.x;
        o.y = (1.f + sc.y) * ((v[i].y - mu) * rstd) + sh.y;
        o.z = (1.f + sc.z) * ((v[i].z - mu) * rstd) + sh.z;
        o.w = (1.f + sc.w) * ((v[i].w - mu) * rstd) + sh.w;
        *(float4*)(g_xmod + (size_t)l * HID + c) = o;
    }
}

// rmsnorm(q,k) + rope + scatter q/k/vT. One block (64 threads) per (head, l); thread j owns pair (2j,2j+1)
__global__ void qkv_prep(const float* __restrict__ pe,
                         const float* __restrict__ qs, const float* __restrict__ ks) {
    const int head = blockIdx.x, l = blockIdx.y, j = threadIdx.x;
    const float* hr = g_h + (size_t)l * H1 + head * HD;
    float q0 = hr[2*j],        q1 = hr[2*j + 1];
    float k0 = hr[HID + 2*j],  k1 = hr[HID + 2*j + 1];
    float v0 = hr[2*HID + 2*j], v1 = hr[2*HID + 2*j + 1];

    float sq = q0*q0 + q1*q1, sk = k0*k0 + k1*k1;
    #pragma unroll
    for (int o = 16; o; o >>= 1) {
        sq += __shfl_down_sync(0xffffffffu, sq, o);
        sk += __shfl_down_sync(0xffffffffu, sk, o);
    }
    __shared__ float red[2][2];
    const int w = j >> 5, lane = j & 31;
    if (!lane) { red[0][w] = sq; red[1][w] = sk; }
    __syncthreads();
    const float rq = rsqrtf((red[0][0] + red[0][1]) * (1.f / HD) + 1e-6f);
    const float rk = rsqrtf((red[1][0] + red[1][1]) * (1.f / HD) + 1e-6f);

    q0 = q0 * rq * qs[2*j]; q1 = q1 * rq * qs[2*j + 1];
    k0 = k0 * rk * ks[2*j]; k1 = k1 * rk * ks[2*j + 1];

    const float* p = pe + ((size_t)l * (HD/2) + j) * 4;   // [j][i0][i1]
    const float p00 = p[0], p01 = p[1], p10 = p[2], p11 = p[3];
    const float qo0 = p00 * q0 + p01 * q1, qo1 = p10 * q0 + p11 * q1;
    const float ko0 = p00 * k0 + p01 * k1, ko1 = p10 * k0 + p11 * k1;

    const float sm = 0.08838834764831845f;  // 1/sqrt(128)
    const size_t qoff = ((size_t)head * SEQL + l) * HD + 2*j;
    g_q[qoff]     = qo0 * sm;  g_q[qoff + 1] = qo1 * sm;
    g_k[qoff]     = ko0;       g_k[qoff + 1] = ko1;
    const size_t voff = ((size_t)head * HD + 2*j) * SEQL + l;
    g_vt[voff]        = v0;
    g_vt[voff + SEQL] = v1;
}

// gelu(mlp half of h) -> concat buffer columns [HID:)
__global__ void gelu_k() {
    const int idx = blockIdx.x * blockDim.x + threadIdx.x;  // float4 id
    const int row = idx / (MLP / 4);
    const int col = (idx % (MLP / 4)) * 4;
    float4 v = *(const float4*)(g_h + (size_t)row * H1 + 3*HID + col);
    v.x = gelu1(v.x); v.y = gelu1(v.y); v.z = gelu1(v.z); v.w = gelu1(v.w);
    *(float4*)(g_c + (size_t)row * C2K + HID + col) = v;
}

// row softmax over 2048, in place on g_s. One block per row.
__global__ __launch_bounds__(256)
void softmax_k() {
    float* p = g_s + (size_t)blockIdx.x * SEQL;
    const int tid = threadIdx.x;
    float4 v0 = *(const float4*)(p + tid * 4);
    float4 v1 = *(const float4*)(p + 1024 + tid * 4);
    float mx = fmaxf(fmaxf(fmaxf(v0.x, v0.y), fmaxf(v0.z, v0.w)),
                     fmaxf(fmaxf(v1.x, v1.y), fmaxf(v1.z, v1.w)));
    __shared__ float rs[8];
    #pragma unroll
    for (int o = 16; o; o >>= 1) mx = fmaxf(mx, __shfl_xor_sync(0xffffffffu, mx, o));
    if (!(tid & 31)) rs[tid >> 5] = mx;
    __syncthreads();
    float gmx = rs[0];
    #pragma unroll
    for (int i = 1; i < 8; ++i) gmx = fmaxf(gmx, rs[i]);
    __syncthreads();
    float sm = 0.f;
    v0.x = __expf(v0.x - gmx); sm += v0.x;  v0.y = __expf(v0.y - gmx); sm += v0.y;
    v0.z = __expf(v0.z - gmx); sm += v0.z;  v0.w = __expf(v0.w - gmx); sm += v0.w;
    v1.x = __expf(v1.x - gmx); sm += v1.x;  v1.y = __expf(v1.y - gmx); sm += v1.y;
    v1.z = __expf(v1.z - gmx); sm += v1.z;  v1.w = __expf(v1.w - gmx); sm += v1.w;
    #pragma unroll
    for (int o = 16; o; o >>= 1) sm += __shfl_xor_sync(0xffffffffu, sm, o);
    if (!(tid & 31)) rs[tid >> 5] = sm;
    __syncthreads();
    float gs = 0.f;
    #pragma unroll
    for (int i = 0; i < 8; ++i) gs += rs[i];
    const float inv = 1.f / gs;
    v0.x *= inv; v0.y *= inv; v0.z *= inv; v0.w *= inv;
    v1.x *= inv; v1.y *= inv; v1.z *= inv; v1.w *= inv;
    *(float4*)(p + tid * 4) = v0;
    *(float4*)(p + 1024 + tid * 4) = v1;
}

// ================= launcher =================
extern "C" void kernel_launch(void* const* d_in, const int* in_sizes, int n_in,
                              void* d_out, int out_size) {
    const float* x       = (const float*)d_in[0];
    const float* vec     = (const float*)d_in[1];
    const float* pe      = (const float*)d_in[2];
    const float* mod_w   = (const float*)d_in[3];
    const float* mod_b   = (const float*)d_in[4];
    const float* lin1_w  = (const float*)d_in[5];
    const float* lin1_b  = (const float*)d_in[6];
    const float* lin2_w  = (const float*)d_in[7];
    const float* lin2_b  = (const float*)d_in[8];
    const float* q_scale = (const float*)d_in[9];
    const float* k_scale = (const float*)d_in[10];
    float* out = (float*)d_out;

    float *p_xmod, *p_h, *p_q, *p_k, *p_vt, *p_s, *p_c, *p_mod;
    cudaGetSymbolAddress((void**)&p_xmod, g_xmod);
    cudaGetSymbolAddress((void**)&p_h,    g_h);
    cudaGetSymbolAddress((void**)&p_q,    g_q);
    cudaGetSymbolAddress((void**)&p_k,    g_k);
    cudaGetSymbolAddress((void**)&p_vt,   g_vt);
    cudaGetSymbolAddress((void**)&p_s,    g_s);
    cudaGetSymbolAddress((void**)&p_c,    g_c);
    cudaGetSymbolAddress((void**)&p_mod,  g_mod);

    // 1) modulation vector
    silu_k<<<HID / 256, 256>>>(vec);
    mod_gemv<<<(3 * HID) / 8, 256>>>(mod_w, mod_b);

    // 2) layernorm + modulation
    ln_mod<<<SEQL, 256>>>(x);

    // 3) lin1: h = x_mod @ lin1_w^T + b   [2048 x 21504]
    gemm_nt<<<dim3(H1 / BN, SEQL / BM, 1), 256>>>(
        p_xmod, lin1_w, lin1_b, nullptr, nullptr, p_h,
        HID, HID, HID, H1, 0, 0, 0);

    // 4) qkv prep (rmsnorm + rope + transpose V) and gelu(mlp)
    qkv_prep<<<dim3(HEADS, SEQL), 64>>>(pe, q_scale, k_scale);
    gelu_k<<<(SEQL * (MLP / 4)) / 256, 256>>>();

    // 5) scores = q @ k^T (batched over heads), softmax-scale folded into q
    gemm_nt<<<dim3(SEQL / BN, SEQL / BM, HEADS), 256>>>(
        p_q, p_k, nullptr, nullptr, nullptr, p_s,
        HD, HD, HD, SEQL,
        (long long)SEQL * HD, (long long)SEQL * HD, (long long)SEQL * SEQL);

    // 6) softmax rows
    softmax_k<<<HEADS * SEQL, 256>>>();

    // 7) attn = P @ V  -> concat buffer columns [0:HID), interleaved by head
    gemm_nt<<<dim3(HD / BN, SEQL / BM, HEADS), 256>>>(
        p_s, p_vt, nullptr, nullptr, nullptr, p_c,
        SEQL, SEQL, SEQL, C2K,
        (long long)SEQL * SEQL, (long long)HD * SEQL, (long long)HD);

    // 8) lin2 + gate + residual fused: out = x + gate * (c @ lin2_w^T + b)
    gemm_nt<<<dim3(HID / BN, SEQL / BM, 1), 256>>>(
        p_c, lin2_w, lin2_b, x, p_mod + 2 * HID, out,
        C2K, C2K, C2K, HID, 0, 0, 0);
}

// round 11
// speedup vs baseline: 2.3061x; 2.3061x over previous
#include <cuda_runtime.h>
#include <cuda_fp16.h>
#include <cstdint>
#include <cstddef>

// ---------------- problem constants ----------------
#define HID   3072
#define HEADS 24
#define HD    128
#define SEQL  2048
#define MLP   12288
#define H1    (3*HID + MLP)   // 21504
#define C2K   (HID + MLP)     // 15360

// ---------------- device scratch (static, no allocations) ----------------
__device__ float  g_svec[HID];
__device__ float  g_mod [3*HID];                        // shift | scale | gate
__device__ float  g_h   [(size_t)SEQL*H1];              // lin1 out (fp32)
__device__ float  g_sf  [(size_t)HEADS*SEQL*SEQL];      // scores fp32
__device__ __half g_xmodh[(size_t)SEQL*HID];            // modulated LN(x), half
__device__ __half g_w1h [(size_t)H1*HID];               // lin1_w half
__device__ __half g_w2h [(size_t)HID*C2K];              // lin2_w half
__device__ __half g_qh  [(size_t)HEADS*SEQL*HD];
__device__ __half g_kh  [(size_t)HEADS*SEQL*HD];
__device__ __half g_vth [(size_t)HEADS*HD*SEQL];        // v transposed [h][d][l]
__device__ __half g_ph  [(size_t)HEADS*SEQL*SEQL];      // probs half
__device__ __half g_ch  [(size_t)SEQL*C2K];             // concat(attn, gelu) half

// ---------------- helpers ----------------
__device__ __forceinline__ uint32_t smem_to_u32(const void* p) {
    uint32_t a;
    asm("{ .reg .u64 t; cvta.to.shared.u64 t, %1; cvt.u32.u64 %0, t; }" : "=r"(a) : "l"(p));
    return a;
}
__device__ __forceinline__ void cp16(uint32_t dst, const void* src) {
    asm volatile("cp.async.cg.shared.global [%0], [%1], 16;" :: "r"(dst), "l"(src) : "memory");
}
#define CP_COMMIT() asm volatile("cp.async.commit_group;" ::: "memory")

__device__ __forceinline__ void mma16(float* d, const uint32_t* a, const uint32_t* b) {
    asm volatile(
        "mma.sync.aligned.m16n8k16.row.col.f32.f16.f16.f32 "
        "{%0,%1,%2,%3}, {%4,%5,%6,%7}, {%8,%9}, {%0,%1,%2,%3};\n"
        : "+f"(d[0]), "+f"(d[1]), "+f"(d[2]), "+f"(d[3])
        : "r"(a[0]), "r"(a[1]), "r"(a[2]), "r"(a[3]), "r"(b[0]), "r"(b[1]));
}

__device__ __forceinline__ float gelu1(float x) {
    float x3 = x * x * x;
    return 0.5f * x * (1.f + tanhf(0.7978845608028654f * (x + 0.044715f * x3)));
}

// ================== FP16 tensor-core NT GEMM ==================
// C[b,m,n] = sum_k A[b,m,k]*B[b,n,k]  (+bias[n])(*gate[n])(+resid[m,n])
// A,B half. Out: fp32 (Cf) or half (Ch). 128x128 tile, K stages of 32,
// double-buffered cp.async, 8 warps with 64x32 warp tiles.
#define BKH   32
#define LDS_K 40   // padded row stride in halves (conflict-free fragment LDS)
#define STG_B (128*LDS_K*2)  // 10240 bytes per stage per operand

__global__ __launch_bounds__(256, 2)
void gemm_h(const __half* __restrict__ A, const __half* __restrict__ B,
            const float* __restrict__ bias, const float* __restrict__ resid,
            const float* __restrict__ gate,
            float* __restrict__ Cf, __half* __restrict__ Ch,
            int K, int lda, int ldb, int ldc,
            long long sA, long long sB, long long sC)
{
    __shared__ __half As[2][128][LDS_K];
    __shared__ __half Bs[2][128][LDS_K];

    const int tid  = threadIdx.x;
    const int lane = tid & 31;
    const int gid  = lane >> 2;
    const int tg   = lane & 3;
    const int warp = tid >> 5;
    const int wm   = (warp >> 2) * 64;   // 0 or 64
    const int wn   = (warp & 3) * 32;    // 0..96

    const int bm0 = blockIdx.x * 128;
    const int bn0 = blockIdx.y * 128;
    const __half* Ab = A + (size_t)blockIdx.z * sA + (size_t)bm0 * lda;
    const __half* Bb = B + (size_t)blockIdx.z * sB + (size_t)bn0 * ldb;

    const uint32_t sAb = smem_to_u32(&As[0][0][0]);
    const uint32_t sBb = smem_to_u32(&Bs[0][0][0]);

    const int fr = tid >> 2;        // 0..63 (also +64)
    const int fq = (tid & 3) * 8;   // half offset within 32-half row

    float acc[4][4][4];
#pragma unroll
    for (int i = 0; i < 4; ++i)
#pragma unroll
        for (int j = 0; j < 4; ++j)
#pragma unroll
            for (int v = 0; v < 4; ++v) acc[i][j][v] = 0.f;

    const int nk = K / BKH;

    // prologue: stages 0 and 1
#pragma unroll
    for (int st = 0; st < 2; ++st) {
        const int k0 = st * BKH;
#pragma unroll
        for (int i = 0; i < 2; ++i) {
            const int r = fr + 64 * i;
            cp16(sAb + st * STG_B + r * (LDS_K*2) + fq * 2, Ab + (size_t)r * lda + k0 + fq);
            cp16(sBb + st * STG_B + r * (LDS_K*2) + fq * 2, Bb + (size_t)r * ldb + k0 + fq);
        }
        CP_COMMIT();
    }

    for (int kt = 0; kt < nk; ++kt) {
        const int s = kt & 1;
        if (kt == nk - 1) asm volatile("cp.async.wait_group 0;" ::: "memory");
        else              asm volatile("cp.async.wait_group 1;" ::: "memory");
        __syncthreads();

#pragma unroll
        for (int ks = 0; ks < 2; ++ks) {
            const int kb = ks * 16 + 2 * tg;
            uint32_t af[4][4];
#pragma unroll
            for (int im = 0; im < 4; ++im) {
                const int m = wm + im * 16 + gid;
                const __half* ap = &As[s][m][kb];
                af[im][0] = *(const uint32_t*)(ap);
                af[im][1] = *(const uint32_t*)(ap + 8 * LDS_K);
                af[im][2] = *(const uint32_t*)(ap + 8);
                af[im][3] = *(const uint32_t*)(ap + 8 * LDS_K + 8);
            }
            uint32_t bf[4][2];
#pragma unroll
            for (int in = 0; in < 4; ++in) {
                const int n = wn + in * 8 + gid;
                const __half* bp = &Bs[s][n][kb];
                bf[in][0] = *(const uint32_t*)(bp);
                bf[in][1] = *(const uint32_t*)(bp + 8);
            }
#pragma unroll
            for (int im = 0; im < 4; ++im)
#pragma unroll
                for (int in = 0; in < 4; ++in)
                    mma16(acc[im][in], af[im], bf[in]);
        }
        __syncthreads();
        if (kt + 2 < nk) {
            const int k0 = (kt + 2) * BKH;
#pragma unroll
            for (int i = 0; i < 2; ++i) {
                const int r = fr + 64 * i;
                cp16(sAb + s * STG_B + r * (LDS_K*2) + fq * 2, Ab + (size_t)r * lda + k0 + fq);
                cp16(sBb + s * STG_B + r * (LDS_K*2) + fq * 2, Bb + (size_t)r * ldb + k0 + fq);
            }
            CP_COMMIT();
        }
    }

    // epilogue
    if (Ch) {
        __half* Cb = Ch + (size_t)blockIdx.z * sC;
#pragma unroll
        for (int im = 0; im < 4; ++im)
#pragma unroll
            for (int in = 0; in < 4; ++in) {
                const int r = bm0 + wm + im * 16 + gid;
                const int c = bn0 + wn + in * 8 + 2 * tg;
                *(__half2*)(Cb + (size_t)r * ldc + c) =
                    __floats2half2_rn(acc[im][in][0], acc[im][in][1]);
                *(__half2*)(Cb + (size_t)(r + 8) * ldc + c) =
                    __floats2half2_rn(acc[im][in][2], acc[im][in][3]);
            }
    } else {
        float* Cb = Cf + (size_t)blockIdx.z * sC;
#pragma unroll
        for (int im = 0; im < 4; ++im)
#pragma unroll
            for (int in = 0; in < 4; ++in) {
                const int r  = bm0 + wm + im * 16 + gid;
                const int cc = bn0 + wn + in * 8 + 2 * tg;
#pragma unroll
                for (int v = 0; v < 4; ++v) {
                    const int rr = r + (v >> 1) * 8;
                    const int c2 = cc + (v & 1);
                    float val = acc[im][in][v];
                    if (bias)  val += __ldg(bias + c2);
                    if (gate)  val *= __ldg(gate + c2);
                    if (resid) val += __ldg(resid + (size_t)rr * ldc + c2);
                    Cb[(size_t)rr * ldc + c2] = val;
                }
            }
    }
}

// ================= small kernels =================

// float -> half, 4 elems/thread
__global__ void conv_f2h(const float* __restrict__ src, __half* __restrict__ dst) {
    const size_t i = (size_t)blockIdx.x * blockDim.x + threadIdx.x;
    float4 v = ((const float4*)src)[i];
    ((__half2*)dst)[2*i]   = __floats2half2_rn(v.x, v.y);
    ((__half2*)dst)[2*i+1] = __floats2half2_rn(v.z, v.w);
}

__global__ void silu_k(const float* __restrict__ v) {
    int i = blockIdx.x * blockDim.x + threadIdx.x;
    float x = v[i];
    g_svec[i] = x / (1.f + __expf(-x));
}

__global__ __launch_bounds__(256)
void mod_gemv(const float* __restrict__ W, const float* __restrict__ b) {
    const int warp = threadIdx.x >> 5, lane = threadIdx.x & 31;
    const int row  = blockIdx.x * 8 + warp;
    const float* w = W + (size_t)row * HID;
    float s = 0.f;
    for (int j = lane * 4; j < HID; j += 128) {
        float4 wv = *(const float4*)(w + j);
        float4 vv = *(const float4*)(g_svec + j);
        s += wv.x * vv.x + wv.y * vv.y + wv.z * vv.z + wv.w * vv.w;
    }
    #pragma unroll
    for (int o = 16; o; o >>= 1) s += __shfl_down_sync(0xffffffffu, s, o);
    if (!lane) g_mod[row] = s + b[row];
}

// x_mod = (1+scale)*LN(x) + shift -> half
__global__ __launch_bounds__(256)
void ln_mod(const float* __restrict__ x) {
    const int l = blockIdx.x, tid = threadIdx.x;
    const float* xr = x + (size_t)l * HID;
    float4 v[3];
    float sum = 0.f, ss = 0.f;
    #pragma unroll
    for (int i = 0; i < 3; ++i) {
        v[i] = *(const float4*)(xr + (tid + i * 256) * 4);
        sum += v[i].x + v[i].y + v[i].z + v[i].w;
        ss  += v[i].x * v[i].x + v[i].y * v[i].y + v[i].z * v[i].z + v[i].w * v[i].w;
    }
    __shared__ float rs[2][8];
    #pragma unroll
    for (int o = 16; o; o >>= 1) {
        sum += __shfl_down_sync(0xffffffffu, sum, o);
        ss  += __shfl_down_sync(0xffffffffu, ss,  o);
    }
    if (!(tid & 31)) { rs[0][tid >> 5] = sum; rs[1][tid >> 5] = ss; }
    __syncthreads();
    sum = 0.f; ss = 0.f;
    #pragma unroll
    for (int i = 0; i < 8; ++i) { sum += rs[0][i]; ss += rs[1][i]; }
    const float mu   = sum * (1.f / HID);
    const float var  = ss * (1.f / HID) - mu * mu;
    const float rstd = rsqrtf(var + 1e-6f);
    #pragma unroll
    for (int i = 0; i < 3; ++i) {
        const int c = (tid + i * 256) * 4;
        float4 sh = *(const float4*)(g_mod + c);
        float4 sc = *(const float4*)(g_mod + HID + c);
        float ox = (1.f + sc.x) * ((v[i].x - mu) * rstd) + sh.x;
        float oy = (1.f + sc.y) * ((v[i].y - mu) * rstd) + sh.y;
        float oz = (1.f + sc.z) * ((v[i].z - mu) * rstd) + sh.z;
        float ow = (1.f + sc.w) * ((v[i].w - mu) * rstd) + sh.w;
        __half2* p = (__half2*)(g_xmodh + (size_t)l * HID + c);
        p[0] = __floats2half2_rn(ox, oy);
        p[1] = __floats2half2_rn(oz, ow);
    }
}

// rmsnorm(q,k) + rope + scatter q/k/vT as half
__global__ void qkv_prep(const float* __restrict__ pe,
                         const float* __restrict__ qs, const float* __restrict__ ks) {
    const int head = blockIdx.x, l = blockIdx.y, j = threadIdx.x;
    const float* hr = g_h + (size_t)l * H1 + head * HD;
    float q0 = hr[2*j],        q1 = hr[2*j + 1];
    float k0 = hr[HID + 2*j],  k1 = hr[HID + 2*j + 1];
    float v0 = hr[2*HID + 2*j], v1 = hr[2*HID + 2*j + 1];

    float sq = q0*q0 + q1*q1, sk = k0*k0 + k1*k1;
    #pragma unroll
    for (int o = 16; o; o >>= 1) {
        sq += __shfl_down_sync(0xffffffffu, sq, o);
        sk += __shfl_down_sync(0xffffffffu, sk, o);
    }
    __shared__ float red[2][2];
    const int w = j >> 5, lane = j & 31;
    if (!lane) { red[0][w] = sq; red[1][w] = sk; }
    __syncthreads();
    const float rq = rsqrtf((red[0][0] + red[0][1]) * (1.f / HD) + 1e-6f);
    const float rk = rsqrtf((red[1][0] + red[1][1]) * (1.f / HD) + 1e-6f);

    q0 = q0 * rq * qs[2*j]; q1 = q1 * rq * qs[2*j + 1];
    k0 = k0 * rk * ks[2*j]; k1 = k1 * rk * ks[2*j + 1];

    const float* p = pe + ((size_t)l * (HD/2) + j) * 4;
    const float p00 = p[0], p01 = p[1], p10 = p[2], p11 = p[3];
    const float qo0 = p00 * q0 + p01 * q1, qo1 = p10 * q0 + p11 * q1;
    const float ko0 = p00 * k0 + p01 * k1, ko1 = p10 * k0 + p11 * k1;

    const float sm = 0.08838834764831845f;  // 1/sqrt(128)
    const size_t qoff = ((size_t)head * SEQL + l) * HD + 2*j;
    *(__half2*)(g_qh + qoff) = __floats2half2_rn(qo0 * sm, qo1 * sm);
    *(__half2*)(g_kh + qoff) = __floats2half2_rn(ko0, ko1);
    const size_t voff = ((size_t)head * HD + 2*j) * SEQL + l;
    g_vth[voff]        = __float2half_rn(v0);
    g_vth[voff + SEQL] = __float2half_rn(v1);
}

// gelu(mlp half of h) -> half concat buffer cols [HID:)
__global__ void gelu_k() {
    const int idx = blockIdx.x * blockDim.x + threadIdx.x;  // float4 id
    const int row = idx / (MLP / 4);
    const int col = (idx % (MLP / 4)) * 4;
    float4 v = *(const float4*)(g_h + (size_t)row * H1 + 3*HID + col);
    __half2* p = (__half2*)(g_ch + (size_t)row * C2K + HID + col);
    p[0] = __floats2half2_rn(gelu1(v.x), gelu1(v.y));
    p[1] = __floats2half2_rn(gelu1(v.z), gelu1(v.w));
}

// row softmax: read fp32 scores, write half probs
__global__ __launch_bounds__(256)
void softmax_k() {
    const float* p = g_sf + (size_t)blockIdx.x * SEQL;
    __half2* q = (__half2*)(g_ph + (size_t)blockIdx.x * SEQL);
    const int tid = threadIdx.x;
    float4 v0 = *(const float4*)(p + tid * 4);
    float4 v1 = *(const float4*)(p + 1024 + tid * 4);
    float mx = fmaxf(fmaxf(fmaxf(v0.x, v0.y), fmaxf(v0.z, v0.w)),
                     fmaxf(fmaxf(v1.x, v1.y), fmaxf(v1.z, v1.w)));
    __shared__ float rs[8];
    #pragma unroll
    for (int o = 16; o; o >>= 1) mx = fmaxf(mx, __shfl_xor_sync(0xffffffffu, mx, o));
    if (!(tid & 31)) rs[tid >> 5] = mx;
    __syncthreads();
    float gmx = rs[0];
    #pragma unroll
    for (int i = 1; i < 8; ++i) gmx = fmaxf(gmx, rs[i]);
    __syncthreads();
    float sm = 0.f;
    v0.x = __expf(v0.x - gmx); sm += v0.x;  v0.y = __expf(v0.y - gmx); sm += v0.y;
    v0.z = __expf(v0.z - gmx); sm += v0.z;  v0.w = __expf(v0.w - gmx); sm += v0.w;
    v1.x = __expf(v1.x - gmx); sm += v1.x;  v1.y = __expf(v1.y - gmx); sm += v1.y;
    v1.z = __expf(v1.z - gmx); sm += v1.z;  v1.w = __expf(v1.w - gmx); sm += v1.w;
    #pragma unroll
    for (int o = 16; o; o >>= 1) sm += __shfl_xor_sync(0xffffffffu, sm, o);
    if (!(tid & 31)) rs[tid >> 5] = sm;
    __syncthreads();
    float gs = 0.f;
    #pragma unroll
    for (int i = 0; i < 8; ++i) gs += rs[i];
    const float inv = 1.f / gs;
    q[tid*2]       = __floats2half2_rn(v0.x * inv, v0.y * inv);
    q[tid*2+1]     = __floats2half2_rn(v0.z * inv, v0.w * inv);
    q[512+tid*2]   = __floats2half2_rn(v1.x * inv, v1.y * inv);
    q[512+tid*2+1] = __floats2half2_rn(v1.z * inv, v1.w * inv);
}

// ================= launcher =================
extern "C" void kernel_launch(void* const* d_in, const int* in_sizes, int n_in,
                              void* d_out, int out_size) {
    const float* x       = (const float*)d_in[0];
    const float* vec     = (const float*)d_in[1];
    const float* pe      = (const float*)d_in[2];
    const float* mod_w   = (const float*)d_in[3];
    const float* mod_b   = (const float*)d_in[4];
    const float* lin1_w  = (const float*)d_in[5];
    const float* lin1_b  = (const float*)d_in[6];
    const float* lin2_w  = (const float*)d_in[7];
    const float* lin2_b  = (const float*)d_in[8];
    const float* q_scale = (const float*)d_in[9];
    const float* k_scale = (const float*)d_in[10];
    float* out = (float*)d_out;

    float *p_h, *p_sf, *p_mod;
    __half *p_xmodh, *p_w1h, *p_w2h, *p_qh, *p_kh, *p_vth, *p_ph, *p_ch;
    cudaGetSymbolAddress((void**)&p_h,     g_h);
    cudaGetSymbolAddress((void**)&p_sf,    g_sf);
    cudaGetSymbolAddress((void**)&p_mod,   g_mod);
    cudaGetSymbolAddress((void**)&p_xmodh, g_xmodh);
    cudaGetSymbolAddress((void**)&p_w1h,   g_w1h);
    cudaGetSymbolAddress((void**)&p_w2h,   g_w2h);
    cudaGetSymbolAddress((void**)&p_qh,    g_qh);
    cudaGetSymbolAddress((void**)&p_kh,    g_kh);
    cudaGetSymbolAddress((void**)&p_vth,   g_vth);
    cudaGetSymbolAddress((void**)&p_ph,    g_ph);
    cudaGetSymbolAddress((void**)&p_ch,    g_ch);

    // 0) weight conversions (independent of everything else)
    conv_f2h<<<((size_t)H1 * HID / 4) / 256, 256>>>(lin1_w, p_w1h);
    conv_f2h<<<((size_t)HID * C2K / 4) / 256, 256>>>(lin2_w, p_w2h);

    // 1) modulation vector
    silu_k<<<HID / 256, 256>>>(vec);
    mod_gemv<<<(3 * HID) / 8, 256>>>(mod_w, mod_b);

    // 2) layernorm + modulation -> half
    ln_mod<<<SEQL, 256>>>(x);

    // 3) lin1: h = x_mod @ lin1_w^T + b  [2048 x 21504] (grid.x = M for L2 B-reuse)
    gemm_h<<<dim3(SEQL / 128, H1 / 128, 1), 256>>>(
        p_xmodh, p_w1h, lin1_b, nullptr, nullptr, p_h, nullptr,
        HID, HID, HID, H1, 0, 0, 0);

    // 4) qkv prep + gelu(mlp)
    qkv_prep<<<dim3(HEADS, SEQL), 64>>>(pe, q_scale, k_scale);
    gelu_k<<<(SEQL * (MLP / 4)) / 256, 256>>>();

    // 5) scores = q @ k^T (batched), softmax scale folded into q -> fp32
    gemm_h<<<dim3(SEQL / 128, SEQL / 128, HEADS), 256>>>(
        p_qh, p_kh, nullptr, nullptr, nullptr, p_sf, nullptr,
        HD, HD, HD, SEQL,
        (long long)SEQL * HD, (long long)SEQL * HD, (long long)SEQL * SEQL);

    // 6) softmax rows -> half probs
    softmax_k<<<HEADS * SEQL, 256>>>();

    // 7) attn = P @ V -> half concat buffer cols [0:HID), head-interleaved
    gemm_h<<<dim3(SEQL / 128, 1, HEADS), 256>>>(
        p_ph, p_vth, nullptr, nullptr, nullptr, nullptr, p_ch,
        SEQL, SEQL, SEQL, C2K,
        (long long)SEQL * SEQL, (long long)HD * SEQL, (long long)HD);

    // 8) lin2 + gate + residual fused: out = x + gate * (c @ lin2_w^T + b)
    gemm_h<<<dim3(SEQL / 128, HID / 128, 1), 256>>>(
        p_ch, p_w2h, lin2_b, x, p_mod + 2 * HID, out, nullptr,
        C2K, C2K, C2K, HID, 0, 0, 0);
}

// round 12
// speedup vs baseline: 2.4066x; 1.0436x over previous
#include <cuda_runtime.h>
#include <cuda_fp16.h>
#include <cstdint>
#include <cstddef>

// ---------------- problem constants ----------------
#define HID   3072
#define HEADS 24
#define HD    128
#define SEQL  2048
#define MLP   12288
#define H1Q   (3*HID)         // 9216  qkv part of lin1
#define C2K   (HID + MLP)     // 15360

// ---------------- device scratch (static, no allocations) ----------------
__device__ float  g_svec[HID];
__device__ float  g_mod [3*HID];                        // shift | scale | gate
__device__ float  g_sf  [(size_t)HEADS*SEQL*SEQL];      // scores fp32
__device__ __half g_xmodh[(size_t)SEQL*HID];            // modulated LN(x)
__device__ __half g_w1h [(size_t)(H1Q+MLP)*HID];        // lin1_w half
__device__ __half g_w2h [(size_t)HID*C2K];              // lin2_w half
__device__ __half g_qkvh[(size_t)SEQL*H1Q];             // lin1 qkv out (half)
__device__ __half g_qh  [(size_t)HEADS*SEQL*HD];
__device__ __half g_kh  [(size_t)HEADS*SEQL*HD];
__device__ __half g_vth [(size_t)HEADS*HD*SEQL];        // v transposed [h][d][l]
__device__ __half g_ph  [(size_t)HEADS*SEQL*SEQL];      // probs half
__device__ __half g_ch  [(size_t)SEQL*C2K];             // concat(attn, gelu)

// ---------------- helpers ----------------
__device__ __forceinline__ uint32_t smem_to_u32(const void* p) {
    uint32_t a;
    asm("{ .reg .u64 t; cvta.to.shared.u64 t, %1; cvt.u32.u64 %0, t; }" : "=r"(a) : "l"(p));
    return a;
}
__device__ __forceinline__ void cp16(uint32_t dst, const void* src) {
    asm volatile("cp.async.cg.shared.global [%0], [%1], 16;" :: "r"(dst), "l"(src) : "memory");
}
#define CP_COMMIT() asm volatile("cp.async.commit_group;" ::: "memory")

__device__ __forceinline__ void mma16(float* d, const uint32_t* a, const uint32_t* b) {
    asm volatile(
        "mma.sync.aligned.m16n8k16.row.col.f32.f16.f16.f32 "
        "{%0,%1,%2,%3}, {%4,%5,%6,%7}, {%8,%9}, {%0,%1,%2,%3};\n"
        : "+f"(d[0]), "+f"(d[1]), "+f"(d[2]), "+f"(d[3])
        : "r"(a[0]), "r"(a[1]), "r"(a[2]), "r"(a[3]), "r"(b[0]), "r"(b[1]));
}

__device__ __forceinline__ float gelu1(float x) {
    float x3 = x * x * x;
    return 0.5f * x * (1.f + tanhf(0.7978845608028654f * (x + 0.044715f * x3)));
}

// ================== FP16 tensor-core NT GEMM ==================
// C[b,m,n] = sum_k A[b,m,k]*B[b,n,k]  (+bias[n])(*gate[n])(+resid[m,n])(gelu)
// 128x128 CTA tile, 4 warps of 64x64, 128 threads, K stages of 32,
// double-buffered cp.async. Out: fp32 (Cf) or half (Ch, optional GELU).
#define BKH   32
#define LDS_K 40                 // padded row stride (halves) -> conflict-free LDS
#define ROWS  256                // 128 A rows + 128 B rows
#define STGB  (ROWS*LDS_K*2)     // 20480 B per stage

__global__ __launch_bounds__(128, 2)
void gemm_h(const __half* __restrict__ A, const __half* __restrict__ B,
            const float* __restrict__ bias, const float* __restrict__ resid,
            const float* __restrict__ gate,
            float* __restrict__ Cf, __half* __restrict__ Ch, int do_gelu,
            int K, int lda, int ldb, int ldc,
            long long sA, long long sB, long long sC)
{
    __shared__ __half smbuf[2 * ROWS * LDS_K];
    char* sm = (char*)smbuf;
    const uint32_t sbase = smem_to_u32(smbuf);

    const int tid  = threadIdx.x;
    const int lane = tid & 31;
    const int gid  = lane >> 2;
    const int tg   = lane & 3;
    const int warp = tid >> 5;
    const int wm   = (warp >> 1) * 64;   // 0 or 64
    const int wn   = (warp & 1) * 64;    // 0 or 64

    const int bm0 = blockIdx.x * 128;
    const int bn0 = blockIdx.y * 128;
    const __half* Ab = A + (size_t)blockIdx.z * sA + (size_t)bm0 * lda;
    const __half* Bb = B + (size_t)blockIdx.z * sB + (size_t)bn0 * ldb;

    float acc[4][8][4];
#pragma unroll
    for (int i = 0; i < 4; ++i)
#pragma unroll
        for (int j = 0; j < 8; ++j)
#pragma unroll
            for (int v = 0; v < 4; ++v) acc[i][j][v] = 0.f;

    const int nk = K / BKH;

    // stage loader: 256 rows x 32 halves, 8 cp16 per thread
#define LOAD_STAGE(k0, st) do {                                              \
    _Pragma("unroll")                                                        \
    for (int _i = 0; _i < 8; ++_i) {                                         \
        const int _idx = tid + _i * 128;                                     \
        const int _r = _idx >> 2, _c = _idx & 3;                             \
        const __half* _src = (_r < 128)                                      \
            ? Ab + (size_t)_r * lda + (k0) + _c * 8                          \
            : Bb + (size_t)(_r - 128) * ldb + (k0) + _c * 8;                 \
        cp16(sbase + (st) * STGB + _r * (LDS_K * 2) + _c * 16, _src);        \
    }                                                                        \
    CP_COMMIT();                                                             \
} while (0)

    LOAD_STAGE(0, 0);
    LOAD_STAGE(BKH, 1);

    for (int kt = 0; kt < nk; ++kt) {
        const int s = kt & 1;
        if (kt == nk - 1) asm volatile("cp.async.wait_group 0;" ::: "memory");
        else              asm volatile("cp.async.wait_group 1;" ::: "memory");
        __syncthreads();

        const __half* Ss = (const __half*)(sm + s * STGB);
#pragma unroll
        for (int ks = 0; ks < 2; ++ks) {
            const int kb = ks * 16 + 2 * tg;
            uint32_t af[4][4];
#pragma unroll
            for (int im = 0; im < 4; ++im) {
                const __half* ap = Ss + (wm + im * 16 + gid) * LDS_K + kb;
                af[im][0] = *(const uint32_t*)(ap);
                af[im][1] = *(const uint32_t*)(ap + 8 * LDS_K);
                af[im][2] = *(const uint32_t*)(ap + 8);
                af[im][3] = *(const uint32_t*)(ap + 8 * LDS_K + 8);
            }
            uint32_t bf[8][2];
#pragma unroll
            for (int in = 0; in < 8; ++in) {
                const __half* bp = Ss + (128 + wn + in * 8 + gid) * LDS_K + kb;
                bf[in][0] = *(const uint32_t*)(bp);
                bf[in][1] = *(const uint32_t*)(bp + 8);
            }
#pragma unroll
            for (int im = 0; im < 4; ++im)
#pragma unroll
                for (int in = 0; in < 8; ++in)
                    mma16(acc[im][in], af[im], bf[in]);
        }
        __syncthreads();
        if (kt + 2 < nk) LOAD_STAGE((kt + 2) * BKH, s);
    }
#undef LOAD_STAGE

    // ---------------- epilogue ----------------
    if (Ch) {
        __half* Cb = Ch + (size_t)blockIdx.z * sC;
#pragma unroll
        for (int im = 0; im < 4; ++im)
#pragma unroll
            for (int in = 0; in < 8; ++in) {
                const int r = bm0 + wm + im * 16 + gid;
                const int c = bn0 + wn + in * 8 + 2 * tg;
                float v0 = acc[im][in][0], v1 = acc[im][in][1];
                float v2 = acc[im][in][2], v3 = acc[im][in][3];
                if (bias) {
                    const float2 bb = *(const float2*)(bias + c);
                    v0 += bb.x; v1 += bb.y; v2 += bb.x; v3 += bb.y;
                }
                if (do_gelu) {
                    v0 = gelu1(v0); v1 = gelu1(v1); v2 = gelu1(v2); v3 = gelu1(v3);
                }
                *(__half2*)(Cb + (size_t)r * ldc + c)       = __floats2half2_rn(v0, v1);
                *(__half2*)(Cb + (size_t)(r + 8) * ldc + c) = __floats2half2_rn(v2, v3);
            }
    } else {
        float* Cb = Cf + (size_t)blockIdx.z * sC;
#pragma unroll
        for (int im = 0; im < 4; ++im)
#pragma unroll
            for (int in = 0; in < 8; ++in) {
                const int r = bm0 + wm + im * 16 + gid;
                const int c = bn0 + wn + in * 8 + 2 * tg;
                float v0 = acc[im][in][0], v1 = acc[im][in][1];
                float v2 = acc[im][in][2], v3 = acc[im][in][3];
                if (bias) {
                    const float2 bb = *(const float2*)(bias + c);
                    v0 += bb.x; v1 += bb.y; v2 += bb.x; v3 += bb.y;
                }
                if (gate) {
                    const float2 gg = *(const float2*)(gate + c);
                    v0 *= gg.x; v1 *= gg.y; v2 *= gg.x; v3 *= gg.y;
                }
                if (resid) {
                    const float2 r0 = *(const float2*)(resid + (size_t)r * ldc + c);
                    const float2 r1 = *(const float2*)(resid + (size_t)(r + 8) * ldc + c);
                    v0 += r0.x; v1 += r0.y; v2 += r1.x; v3 += r1.y;
                }
                *(float2*)(Cb + (size_t)r * ldc + c)       = make_float2(v0, v1);
                *(float2*)(Cb + (size_t)(r + 8) * ldc + c) = make_float2(v2, v3);
            }
    }
}

// ================= small kernels =================

__global__ void conv_f2h(const float* __restrict__ src, __half* __restrict__ dst) {
    const size_t i = (size_t)blockIdx.x * blockDim.x + threadIdx.x;
    float4 v = ((const float4*)src)[i];
    ((__half2*)dst)[2*i]   = __floats2half2_rn(v.x, v.y);
    ((__half2*)dst)[2*i+1] = __floats2half2_rn(v.z, v.w);
}

__global__ void silu_k(const float* __restrict__ v) {
    int i = blockIdx.x * blockDim.x + threadIdx.x;
    float x = v[i];
    g_svec[i] = x / (1.f + __expf(-x));
}

__global__ __launch_bounds__(256)
void mod_gemv(const float* __restrict__ W, const float* __restrict__ b) {
    const int warp = threadIdx.x >> 5, lane = threadIdx.x & 31;
    const int row  = blockIdx.x * 8 + warp;
    const float* w = W + (size_t)row * HID;
    float s = 0.f;
    for (int j = lane * 4; j < HID; j += 128) {
        float4 wv = *(const float4*)(w + j);
        float4 vv = *(const float4*)(g_svec + j);
        s += wv.x * vv.x + wv.y * vv.y + wv.z * vv.z + wv.w * vv.w;
    }
    #pragma unroll
    for (int o = 16; o; o >>= 1) s += __shfl_down_sync(0xffffffffu, s, o);
    if (!lane) g_mod[row] = s + b[row];
}

// x_mod = (1+scale)*LN(x) + shift -> half
__global__ __launch_bounds__(256)
void ln_mod(const float* __restrict__ x) {
    const int l = blockIdx.x, tid = threadIdx.x;
    const float* xr = x + (size_t)l * HID;
    float4 v[3];
    float sum = 0.f, ss = 0.f;
    #pragma unroll
    for (int i = 0; i < 3; ++i) {
        v[i] = *(const float4*)(xr + (tid + i * 256) * 4);
        sum += v[i].x + v[i].y + v[i].z + v[i].w;
        ss  += v[i].x * v[i].x + v[i].y * v[i].y + v[i].z * v[i].z + v[i].w * v[i].w;
    }
    __shared__ float rs[2][8];
    #pragma unroll
    for (int o = 16; o; o >>= 1) {
        sum += __shfl_down_sync(0xffffffffu, sum, o);
        ss  += __shfl_down_sync(0xffffffffu, ss,  o);
    }
    if (!(tid & 31)) { rs[0][tid >> 5] = sum; rs[1][tid >> 5] = ss; }
    __syncthreads();
    sum = 0.f; ss = 0.f;
    #pragma unroll
    for (int i = 0; i < 8; ++i) { sum += rs[0][i]; ss += rs[1][i]; }
    const float mu   = sum * (1.f / HID);
    const float var  = ss * (1.f / HID) - mu * mu;
    const float rstd = rsqrtf(var + 1e-6f);
    #pragma unroll
    for (int i = 0; i < 3; ++i) {
        const int c = (tid + i * 256) * 4;
        float4 sh = *(const float4*)(g_mod + c);
        float4 sc = *(const float4*)(g_mod + HID + c);
        float ox = (1.f + sc.x) * ((v[i].x - mu) * rstd) + sh.x;
        float oy = (1.f + sc.y) * ((v[i].y - mu) * rstd) + sh.y;
        float oz = (1.f + sc.z) * ((v[i].z - mu) * rstd) + sh.z;
        float ow = (1.f + sc.w) * ((v[i].w - mu) * rstd) + sh.w;
        __half2* p = (__half2*)(g_xmodh + (size_t)l * HID + c);
        p[0] = __floats2half2_rn(ox, oy);
        p[1] = __floats2half2_rn(oz, ow);
    }
}

// rmsnorm(q,k) + rope + scatter q/k/vT (reads half qkv)
__global__ void qkv_prep(const float* __restrict__ pe,
                         const float* __restrict__ qs, const float* __restrict__ ks) {
    const int head = blockIdx.x, l = blockIdx.y, j = threadIdx.x;
    const __half* hr = g_qkvh + (size_t)l * H1Q + head * HD;
    float q0 = __half2float(hr[2*j]),         q1 = __half2float(hr[2*j + 1]);
    float k0 = __half2float(hr[HID + 2*j]),   k1 = __half2float(hr[HID + 2*j + 1]);
    float v0 = __half2float(hr[2*HID + 2*j]), v1 = __half2float(hr[2*HID + 2*j + 1]);

    float sq = q0*q0 + q1*q1, sk = k0*k0 + k1*k1;
    #pragma unroll
    for (int o = 16; o; o >>= 1) {
        sq += __shfl_down_sync(0xffffffffu, sq, o);
        sk += __shfl_down_sync(0xffffffffu, sk, o);
    }
    __shared__ float red[2][2];
    const int w = j >> 5, lane = j & 31;
    if (!lane) { red[0][w] = sq; red[1][w] = sk; }
    __syncthreads();
    const float rq = rsqrtf((red[0][0] + red[0][1]) * (1.f / HD) + 1e-6f);
    const float rk = rsqrtf((red[1][0] + red[1][1]) * (1.f / HD) + 1e-6f);

    q0 = q0 * rq * qs[2*j]; q1 = q1 * rq * qs[2*j + 1];
    k0 = k0 * rk * ks[2*j]; k1 = k1 * rk * ks[2*j + 1];

    const float* p = pe + ((size_t)l * (HD/2) + j) * 4;
    const float p00 = p[0], p01 = p[1], p10 = p[2], p11 = p[3];
    const float qo0 = p00 * q0 + p01 * q1, qo1 = p10 * q0 + p11 * q1;
    const float ko0 = p00 * k0 + p01 * k1, ko1 = p10 * k0 + p11 * k1;

    const float sm = 0.08838834764831845f;  // 1/sqrt(128)
    const size_t qoff = ((size_t)head * SEQL + l) * HD + 2*j;
    *(__half2*)(g_qh + qoff) = __floats2half2_rn(qo0 * sm, qo1 * sm);
    *(__half2*)(g_kh + qoff) = __floats2half2_rn(ko0, ko1);
    const size_t voff = ((size_t)head * HD + 2*j) * SEQL + l;
    g_vth[voff]        = __float2half_rn(v0);
    g_vth[voff + SEQL] = __float2half_rn(v1);
}

// row softmax: fp32 scores in, half probs out
__global__ __launch_bounds__(256)
void softmax_k() {
    const float* p = g_sf + (size_t)blockIdx.x * SEQL;
    __half2* q = (__half2*)(g_ph + (size_t)blockIdx.x * SEQL);
    const int tid = threadIdx.x;
    float4 v0 = *(const float4*)(p + tid * 4);
    float4 v1 = *(const float4*)(p + 1024 + tid * 4);
    float mx = fmaxf(fmaxf(fmaxf(v0.x, v0.y), fmaxf(v0.z, v0.w)),
                     fmaxf(fmaxf(v1.x, v1.y), fmaxf(v1.z, v1.w)));
    __shared__ float rs[8];
    #pragma unroll
    for (int o = 16; o; o >>= 1) mx = fmaxf(mx, __shfl_xor_sync(0xffffffffu, mx, o));
    if (!(tid & 31)) rs[tid >> 5] = mx;
    __syncthreads();
    float gmx = rs[0];
    #pragma unroll
    for (int i = 1; i < 8; ++i) gmx = fmaxf(gmx, rs[i]);
    __syncthreads();
    float sm = 0.f;
    v0.x = __expf(v0.x - gmx); sm += v0.x;  v0.y = __expf(v0.y - gmx); sm += v0.y;
    v0.z = __expf(v0.z - gmx); sm += v0.z;  v0.w = __expf(v0.w - gmx); sm += v0.w;
    v1.x = __expf(v1.x - gmx); sm += v1.x;  v1.y = __expf(v1.y - gmx); sm += v1.y;
    v1.z = __expf(v1.z - gmx); sm += v1.z;  v1.w = __expf(v1.w - gmx); sm += v1.w;
    #pragma unroll
    for (int o = 16; o; o >>= 1) sm += __shfl_xor_sync(0xffffffffu, sm, o);
    if (!(tid & 31)) rs[tid >> 5] = sm;
    __syncthreads();
    float gs = 0.f;
    #pragma unroll
    for (int i = 0; i < 8; ++i) gs += rs[i];
    const float inv = 1.f / gs;
    q[tid*2]       = __floats2half2_rn(v0.x * inv, v0.y * inv);
    q[tid*2+1]     = __floats2half2_rn(v0.z * inv, v0.w * inv);
    q[512+tid*2]   = __floats2half2_rn(v1.x * inv, v1.y * inv);
    q[512+tid*2+1] = __floats2half2_rn(v1.z * inv, v1.w * inv);
}

// ================= launcher =================
extern "C" void kernel_launch(void* const* d_in, const int* in_sizes, int n_in,
                              void* d_out, int out_size) {
    const float* x       = (const float*)d_in[0];
    const float* vec     = (const float*)d_in[1];
    const float* pe      = (const float*)d_in[2];
    const float* mod_w   = (const float*)d_in[3];
    const float* mod_b   = (const float*)d_in[4];
    const float* lin1_w  = (const float*)d_in[5];
    const float* lin1_b  = (const float*)d_in[6];
    const float* lin2_w  = (const float*)d_in[7];
    const float* lin2_b  = (const float*)d_in[8];
    const float* q_scale = (const float*)d_in[9];
    const float* k_scale = (const float*)d_in[10];
    float* out = (float*)d_out;

    float *p_sf, *p_mod;
    __half *p_xmodh, *p_w1h, *p_w2h, *p_qkvh, *p_qh, *p_kh, *p_vth, *p_ph, *p_ch;
    cudaGetSymbolAddress((void**)&p_sf,    g_sf);
    cudaGetSymbolAddress((void**)&p_mod,   g_mod);
    cudaGetSymbolAddress((void**)&p_xmodh, g_xmodh);
    cudaGetSymbolAddress((void**)&p_w1h,   g_w1h);
    cudaGetSymbolAddress((void**)&p_w2h,   g_w2h);
    cudaGetSymbolAddress((void**)&p_qkvh,  g_qkvh);
    cudaGetSymbolAddress((void**)&p_qh,    g_qh);
    cudaGetSymbolAddress((void**)&p_kh,    g_kh);
    cudaGetSymbolAddress((void**)&p_vth,   g_vth);
    cudaGetSymbolAddress((void**)&p_ph,    g_ph);
    cudaGetSymbolAddress((void**)&p_ch,    g_ch);

    // 0) weight conversions
    conv_f2h<<<((size_t)(H1Q + MLP) * HID / 4) / 256, 256>>>(lin1_w, p_w1h);
    conv_f2h<<<((size_t)HID * C2K / 4) / 256, 256>>>(lin2_w, p_w2h);

    // 1) modulation vector
    silu_k<<<HID / 256, 256>>>(vec);
    mod_gemv<<<(3 * HID) / 8, 256>>>(mod_w, mod_b);

    // 2) layernorm + modulation -> half
    ln_mod<<<SEQL, 256>>>(x);

    // 3a) lin1 qkv part: [2048 x 9216] -> half, bias fused
    gemm_h<<<dim3(SEQL / 128, H1Q / 128, 1), 128>>>(
        p_xmodh, p_w1h, lin1_b, nullptr, nullptr, nullptr, p_qkvh, 0,
        HID, HID, HID, H1Q, 0, 0, 0);

    // 3b) lin1 mlp part: [2048 x 12288] -> half with fused bias+GELU,
    //     written straight into concat buffer cols [HID:)
    gemm_h<<<dim3(SEQL / 128, MLP / 128, 1), 128>>>(
        p_xmodh, p_w1h + (size_t)H1Q * HID, lin1_b + H1Q, nullptr, nullptr,
        nullptr, p_ch + HID, 1,
        HID, HID, HID, C2K, 0, 0, 0);

    // 4) qkv prep (rmsnorm + rope + V transpose)
    qkv_prep<<<dim3(HEADS, SEQL), 64>>>(pe, q_scale, k_scale);

    // 5) scores = q @ k^T (batched over heads) -> fp32
    gemm_h<<<dim3(SEQL / 128, SEQL / 128, HEADS), 128>>>(
        p_qh, p_kh, nullptr, nullptr, nullptr, p_sf, nullptr, 0,
        HD, HD, HD, SEQL,
        (long long)SEQL * HD, (long long)SEQL * HD, (long long)SEQL * SEQL);

    // 6) softmax -> half probs
    softmax_k<<<HEADS * SEQL, 256>>>();

    // 7) attn = P @ V -> half concat buffer cols [0:HID), head-interleaved
    gemm_h<<<dim3(SEQL / 128, HD / 128, HEADS), 128>>>(
        p_ph, p_vth, nullptr, nullptr, nullptr, nullptr, p_ch, 0,
        SEQL, SEQL, SEQL, C2K,
        (long long)SEQL * SEQL, (long long)HD * SEQL, (long long)HD);

    // 8) lin2 + gate + residual fused: out = x + gate * (c @ lin2_w^T + b)
    gemm_h<<<dim3(SEQL / 128, HID / 128, 1), 128>>>(
        p_ch, p_w2h, lin2_b, x, p_mod + 2 * HID, out, nullptr, 0,
        C2K, C2K, C2K, HID, 0, 0, 0);
}